// round 6
// baseline (speedup 1.0000x reference)
#include <cuda_runtime.h>
#include <cuda_fp16.h>
#include <cstdint>
#include <math.h>
#include <float.h>

#define Lq 512
#define Bq 8
#define Nq 32
#define Dq 256
#define GHq 128
#define AHq 64
#define KC 512
#define THREADS 256

// fp16 weights, [n][k] k-contiguous (fp16 single-pass: input-rounding errors
// average incoherently over K, rel err ~7e-5 << 1e-3)
__device__ __half g_w1h[GHq * KC];
__device__ __half g_w2h[AHq * Dq];
__device__ int g_mask_mode;  // 0 = byte bool, 1 = int32, 2 = float32

__global__ void prep_kernel(const float* __restrict__ gw1, const float* __restrict__ aw1,
                            const unsigned char* __restrict__ mask_raw) {
    int i = blockIdx.x * blockDim.x + threadIdx.x;
    if (i < GHq * KC) g_w1h[i] = __float2half_rn(gw1[i]);
    if (i < AHq * Dq) g_w2h[i] = __float2half_rn(aw1[i]);
    if (blockIdx.x == 0 && threadIdx.x == 0) {
        bool anyFloatSig = false, anyOffNonzero = false;
        for (int j = 0; j < 4096; j++) {
            unsigned char c = mask_raw[j];
            if ((j & 3) != 0) {
                if (c == 0x3Fu || c == 0x80u) anyFloatSig = true;
                if (c != 0) anyOffNonzero = true;
            }
        }
        g_mask_mode = anyFloatSig ? 2 : (anyOffNonzero ? 0 : 1);
    }
}

__device__ __forceinline__ uint32_t smem_u32(const void* p) {
    return (uint32_t)__cvta_generic_to_shared(p);
}
__device__ __forceinline__ void ldmatrix_x4(uint32_t* r, uint32_t addr) {
    asm volatile("ldmatrix.sync.aligned.m8n8.x4.shared.b16 {%0,%1,%2,%3}, [%4];"
                 : "=r"(r[0]), "=r"(r[1]), "=r"(r[2]), "=r"(r[3]) : "r"(addr));
}
__device__ __forceinline__ void mma16816(float* c, const uint32_t* a, uint32_t b0, uint32_t b1) {
    asm volatile("mma.sync.aligned.m16n8k16.row.col.f32.f16.f16.f32 "
                 "{%0,%1,%2,%3},{%4,%5,%6,%7},{%8,%9},{%0,%1,%2,%3};"
                 : "+f"(c[0]), "+f"(c[1]), "+f"(c[2]), "+f"(c[3])
                 : "r"(a[0]), "r"(a[1]), "r"(a[2]), "r"(a[3]), "r"(b0), "r"(b1));
}

// SMEM: A tile [64][72] fp16, W tile [128][72] fp16 (stride 72 = conflict-free ldmatrix)
#define A_STRIDE 72
#define W_STRIDE 72
#define OFF_A 0
#define OFF_W (64 * A_STRIDE * 2)
#define OFF_GPART (OFF_W + 128 * W_STRIDE * 2)     // float [64][4]
#define OFF_GATE (OFF_GPART + 64 * 4 * 4)          // float [64]
#define OFF_ATTN (OFF_GATE + 64 * 4)               // float [64]
#define SMEM_TOTAL (OFF_ATTN + 64 * 4)

__global__ __launch_bounds__(THREADS, 4)
void fusion_main(const float* __restrict__ vert, const float* __restrict__ horiz,
                 const unsigned char* __restrict__ mask,
                 const float* __restrict__ gb1, const float* __restrict__ gw2,
                 const float* __restrict__ gb2,
                 const float* __restrict__ ab1, const float* __restrict__ aw2,
                 const float* __restrict__ ab2,
                 float* __restrict__ out_fused, float* __restrict__ out_pm,
                 float* __restrict__ out_attn) {
    extern __shared__ char smem[];
    __half* As = (__half*)(smem + OFF_A);
    __half* Ws = (__half*)(smem + OFF_W);
    float* gpart = (float*)(smem + OFF_GPART);
    float* gate_s = (float*)(smem + OFF_GATE);
    float* attn_s = (float*)(smem + OFF_ATTN);

    const int tid = threadIdx.x;
    const int wid = tid >> 5;
    const int lane = tid & 31;
    const int cta = blockIdx.x;          // 2 lb pairs: lb = cta*2 + lbi

    // GEMM1 warp grid: 2(m) x 4(n); warp tile m32 x n32
    const int mg = wid >> 2;
    const int ng = wid & 3;

    // ldmatrix A addressing (m16 x k16 tile)
    const int lgrp = lane >> 3;
    const int lrow = (lane & 7) + (lgrp & 1) * 8;
    const int lcol = (lgrp >> 1) * 8;
    // ldmatrix B addressing (n16 x k16 tile pair)
    const int bn_off = ((lane >> 4) & 1) * 8 + (lane & 7);
    const int bk_off = ((lane >> 3) & 1) * 8;

    // ================= GEMM1: C1[64][128] = concat(V,H) @ gw1^T =================
    float acc[2][4][4];
#pragma unroll
    for (int a = 0; a < 2; a++)
#pragma unroll
        for (int b = 0; b < 4; b++)
#pragma unroll
            for (int c = 0; c < 4; c++) acc[a][b][c] = 0.f;

#pragma unroll 1
    for (int chunk = 0; chunk < 8; chunk++) {
        const float* feat = (chunk < 4) ? vert : horiz;
        const int kb = (chunk & 3) * 64;
        __syncthreads();
        // stage A chunk: 64 m x 64 k fp32 -> fp16
        const float4* src = (const float4*)(feat + (size_t)cta * 64 * Dq);
#pragma unroll
        for (int t = 0; t < 4; t++) {
            int j = tid + t * THREADS;           // 0..1023
            int m = j >> 4;
            int kq = (j & 15) * 4;
            float4 v = src[m * (Dq / 4) + (kb + kq) / 4];
            __half2 h01 = __floats2half2_rn(v.x, v.y);
            __half2 h23 = __floats2half2_rn(v.z, v.w);
            *(uint2*)&As[m * A_STRIDE + kq] =
                make_uint2(*(uint32_t*)&h01, *(uint32_t*)&h23);
        }
        // stage W1 chunk: 128 n x 64 k fp16 (uint4 = 8 halves)
        {
            const uint4* s = (const uint4*)g_w1h;
            uint4* d = (uint4*)Ws;
#pragma unroll
            for (int t = 0; t < 4; t++) {
                int j = tid + t * THREADS;       // 0..1023 = 128 rows x 8 uint4
                int n = j >> 3;
                int q = j & 7;
                d[n * 9 + q] = s[n * 64 + chunk * 8 + q];
            }
        }
        __syncthreads();

#pragma unroll
        for (int ks = 0; ks < 4; ks++) {
            const int kk = ks * 16;
            uint32_t a[2][4];
#pragma unroll
            for (int mt = 0; mt < 2; mt++) {
                int row = mg * 32 + mt * 16 + lrow;
                ldmatrix_x4(a[mt], smem_u32(&As[row * A_STRIDE + kk + lcol]));
            }
#pragma unroll
            for (int nh = 0; nh < 2; nh++) {
                uint32_t b[4];
                ldmatrix_x4(b, smem_u32(&Ws[(ng * 32 + nh * 16 + bn_off) * W_STRIDE + kk + bk_off]));
#pragma unroll
                for (int nf2 = 0; nf2 < 2; nf2++) {
                    int nf = nh * 2 + nf2;
#pragma unroll
                    for (int mt = 0; mt < 2; mt++)
                        mma16816(acc[mt][nf], a[mt], b[nf2 * 2], b[nf2 * 2 + 1]);
                }
            }
        }
    }

    // ---- gate epilogue: relu(C1+gb1) . gw2 -> partials -> sigmoid ----
    {
        float p0[2] = {0.f, 0.f}, p1[2] = {0.f, 0.f};
#pragma unroll
        for (int nf = 0; nf < 4; nf++) {
#pragma unroll
            for (int j = 0; j < 2; j++) {
                int n = ng * 32 + nf * 8 + 2 * (lane & 3) + j;
                float b1v = __ldg(&gb1[n]);
                float w2v = __ldg(&gw2[n]);
#pragma unroll
                for (int mt = 0; mt < 2; mt++) {
                    p0[mt] += fmaxf(acc[mt][nf][j] + b1v, 0.f) * w2v;
                    p1[mt] += fmaxf(acc[mt][nf][j + 2] + b1v, 0.f) * w2v;
                }
            }
        }
#pragma unroll
        for (int o = 1; o <= 2; o <<= 1) {
#pragma unroll
            for (int mt = 0; mt < 2; mt++) {
                p0[mt] += __shfl_xor_sync(0xffffffffu, p0[mt], o);
                p1[mt] += __shfl_xor_sync(0xffffffffu, p1[mt], o);
            }
        }
        if ((lane & 3) == 0) {
            int r = lane >> 2;
#pragma unroll
            for (int mt = 0; mt < 2; mt++) {
                gpart[(mg * 32 + mt * 16 + r) * 4 + ng] = p0[mt];
                gpart[(mg * 32 + mt * 16 + 8 + r) * 4 + ng] = p1[mt];
            }
        }
        __syncthreads();
        if (tid < 64) {
            float s = gpart[tid * 4] + gpart[tid * 4 + 1] + gpart[tid * 4 + 2] + gpart[tid * 4 + 3];
            s += __ldg(gb2);
            gate_s[tid] = 1.f / (1.f + __expf(-s));
        }
        __syncthreads();
    }

    // ========== blend + GEMM2 (k-chunked through the A buffer) ==========
    const int ng2 = wid & 3;          // n0 = ng2*16
    const int mg2 = wid >> 2;
    float acc2[2][2][4];
#pragma unroll
    for (int a = 0; a < 2; a++)
#pragma unroll
        for (int b = 0; b < 2; b++)
#pragma unroll
            for (int c = 0; c < 4; c++) acc2[a][b][c] = 0.f;

#pragma unroll 1
    for (int kc = 0; kc < 4; kc++) {
        __syncthreads();
        // blend chunk: p = g*v + (1-g)*h; write pm fp32; stage fp16
        {
            const float4* v4 = (const float4*)(vert + (size_t)cta * 64 * Dq);
            const float4* h4 = (const float4*)(horiz + (size_t)cta * 64 * Dq);
            float4* pm4 = (float4*)(out_pm + (size_t)cta * 64 * Dq);
#pragma unroll
            for (int t = 0; t < 4; t++) {
                int j = tid + t * THREADS;       // 0..1023
                int m = j >> 4;
                int kq = (j & 15) * 4;
                int gi = m * (Dq / 4) + (kc * 64 + kq) / 4;
                float g = gate_s[m];
                float og = 1.f - g;
                float4 v = v4[gi];
                float4 h = h4[gi];
                float4 p;
                p.x = fmaf(g, v.x, og * h.x);
                p.y = fmaf(g, v.y, og * h.y);
                p.z = fmaf(g, v.z, og * h.z);
                p.w = fmaf(g, v.w, og * h.w);
                pm4[gi] = p;
                __half2 h01 = __floats2half2_rn(p.x, p.y);
                __half2 h23 = __floats2half2_rn(p.z, p.w);
                *(uint2*)&As[m * A_STRIDE + kq] =
                    make_uint2(*(uint32_t*)&h01, *(uint32_t*)&h23);
            }
        }
        // stage W2 chunk: 64 n x 64 k
        {
            const uint4* s = (const uint4*)g_w2h;
            uint4* d = (uint4*)Ws;
#pragma unroll
            for (int t = 0; t < 2; t++) {
                int j = tid + t * THREADS;       // 0..511 = 64 rows x 8 uint4
                int n = j >> 3;
                int q = j & 7;
                d[n * 9 + q] = s[n * 32 + kc * 8 + q];
            }
        }
        __syncthreads();

#pragma unroll
        for (int ks = 0; ks < 4; ks++) {
            const int kk = ks * 16;
            uint32_t a[2][4];
#pragma unroll
            for (int mt = 0; mt < 2; mt++) {
                int row = mg2 * 32 + mt * 16 + lrow;
                ldmatrix_x4(a[mt], smem_u32(&As[row * A_STRIDE + kk + lcol]));
            }
            uint32_t b[4];
            ldmatrix_x4(b, smem_u32(&Ws[(ng2 * 16 + bn_off) * W_STRIDE + kk + bk_off]));
#pragma unroll
            for (int nf = 0; nf < 2; nf++) {
#pragma unroll
                for (int mt = 0; mt < 2; mt++)
                    mma16816(acc2[mt][nf], a[mt], b[nf * 2], b[nf * 2 + 1]);
            }
        }
    }

    // ---- logits epilogue: tanh(C2+ab1) . aw2 ----
    {
        float p0[2] = {0.f, 0.f}, p1[2] = {0.f, 0.f};
#pragma unroll
        for (int nf = 0; nf < 2; nf++) {
#pragma unroll
            for (int j = 0; j < 2; j++) {
                int n = ng2 * 16 + nf * 8 + 2 * (lane & 3) + j;
                float b1v = __ldg(&ab1[n]);
                float w2v = __ldg(&aw2[n]);
#pragma unroll
                for (int mt = 0; mt < 2; mt++) {
                    p0[mt] += tanhf(acc2[mt][nf][j] + b1v) * w2v;
                    p1[mt] += tanhf(acc2[mt][nf][j + 2] + b1v) * w2v;
                }
            }
        }
#pragma unroll
        for (int o = 1; o <= 2; o <<= 1) {
#pragma unroll
            for (int mt = 0; mt < 2; mt++) {
                p0[mt] += __shfl_xor_sync(0xffffffffu, p0[mt], o);
                p1[mt] += __shfl_xor_sync(0xffffffffu, p1[mt], o);
            }
        }
        __syncthreads();  // gpart reuse
        if ((lane & 3) == 0) {
            int r = lane >> 2;
#pragma unroll
            for (int mt = 0; mt < 2; mt++) {
                gpart[(mg2 * 32 + mt * 16 + r) * 4 + ng2] = p0[mt];
                gpart[(mg2 * 32 + mt * 16 + 8 + r) * 4 + ng2] = p1[mt];
            }
        }
        __syncthreads();
    }

    // ---- masked softmax per lb (2 warps; lane = msg) ----
    if (tid < 64) {
        int lbi = tid >> 5;
        int msg = tid & 31;
        int lb = cta * 2 + lbi;
        int l = lb >> 3, b = lb & 7;
        float lg = gpart[tid * 4] + gpart[tid * 4 + 1] + gpart[tid * 4 + 2] + gpart[tid * 4 + 3];
        lg += __ldg(ab2);
        size_t midx = ((size_t)b * Nq + msg) * Lq + l;
        int mode = g_mask_mode;
        bool valid;
        if (mode == 2)      valid = ((const float*)mask)[midx] != 0.0f;
        else if (mode == 1) valid = ((const int*)mask)[midx] != 0;
        else                valid = mask[midx] != 0;
        float mv = valid ? lg : -FLT_MAX;
#pragma unroll
        for (int o = 16; o >= 1; o >>= 1)
            mv = fmaxf(mv, __shfl_xor_sync(0xffffffffu, mv, o));
        float e = valid ? __expf(lg - mv) : 0.f;
        float s = e;
#pragma unroll
        for (int o = 16; o >= 1; o >>= 1)
            s += __shfl_xor_sync(0xffffffffu, s, o);
        float a = (s > 0.f) ? e / s : 0.f;
        attn_s[tid] = a;
        out_attn[((size_t)b * Lq + l) * Nq + msg] = a;
    }
    __syncthreads();

    // ---- fused[lb][d] = sum_m attn * per_msg (re-read pm, L2-hot) ----
#pragma unroll
    for (int t = 0; t < 2; t++) {
        int j = tid + t * THREADS;          // 0..511 = 2 lb x 256 d
        int lbi = j >> 8;
        int d = j & 255;
        const float* pmr = out_pm + (size_t)cta * 64 * Dq + (size_t)lbi * 32 * Dq + d;
        float f = 0.f;
#pragma unroll
        for (int m = 0; m < Nq; m++)
            f = fmaf(attn_s[lbi * 32 + m], pmr[m * Dq], f);
        out_fused[(size_t)cta * 512 + j] = f;
    }
}

extern "C" void kernel_launch(void* const* d_in, const int* in_sizes, int n_in,
                              void* d_out, int out_size) {
    const float* vert = (const float*)d_in[0];
    const float* horiz = (const float*)d_in[1];
    const unsigned char* mask = (const unsigned char*)d_in[2];
    const float* gw1 = (const float*)d_in[3];
    const float* gb1 = (const float*)d_in[4];
    const float* gw2 = (const float*)d_in[5];
    const float* gb2 = (const float*)d_in[6];
    const float* aw1 = (const float*)d_in[7];
    const float* ab1 = (const float*)d_in[8];
    const float* aw2 = (const float*)d_in[9];
    const float* ab2 = (const float*)d_in[10];

    float* out = (float*)d_out;
    float* out_fused = out;                                   // L*B*D
    float* out_pm = out + (size_t)Lq * Bq * Dq;               // L*B*N*D
    float* out_attn = out_pm + (size_t)Lq * Bq * Nq * Dq;     // B*L*N

    prep_kernel<<<(GHq * KC + 255) / 256, 256>>>(gw1, aw1, mask);

    cudaFuncSetAttribute(fusion_main, cudaFuncAttributeMaxDynamicSharedMemorySize, SMEM_TOTAL);
    fusion_main<<<Lq * Bq / 2, THREADS, SMEM_TOTAL>>>(vert, horiz, mask,
                                                      gb1, gw2, gb2, ab1, aw2, ab2,
                                                      out_fused, out_pm, out_attn);
}

// round 8
// speedup vs baseline: 1.3912x; 1.3912x over previous
#include <cuda_runtime.h>
#include <cuda_fp16.h>
#include <cstdint>
#include <math.h>
#include <float.h>

#define Lq 512
#define Bq 8
#define Nq 32
#define Dq 256
#define GHq 128
#define AHq 64
#define KC 512
#define THREADS 256

// fp16 weights, [n][k] k-contiguous
__device__ __half g_w1h[GHq * KC];     // [128][512]
__device__ __half g_w2h[AHq * Dq];     // [64][256]
__device__ int g_mask_mode;            // 0 = byte bool, 1 = int32, 2 = float32

__global__ void prep_kernel(const float* __restrict__ gw1, const float* __restrict__ aw1,
                            const unsigned char* __restrict__ mask_raw) {
    int i = blockIdx.x * blockDim.x + threadIdx.x;
    if (i < GHq * KC) g_w1h[i] = __float2half_rn(gw1[i]);
    if (i < AHq * Dq) g_w2h[i] = __float2half_rn(aw1[i]);
    if (blockIdx.x == 0 && threadIdx.x == 0) {
        bool anyFloatSig = false, anyOffNonzero = false;
        for (int j = 0; j < 4096; j++) {
            unsigned char c = mask_raw[j];
            if ((j & 3) != 0) {
                if (c == 0x3Fu || c == 0x80u) anyFloatSig = true;
                if (c != 0) anyOffNonzero = true;
            }
        }
        g_mask_mode = anyFloatSig ? 2 : (anyOffNonzero ? 0 : 1);
    }
}

__device__ __forceinline__ uint32_t smem_u32(const void* p) {
    return (uint32_t)__cvta_generic_to_shared(p);
}
__device__ __forceinline__ void ldmatrix_x4(uint32_t* r, uint32_t addr) {
    asm volatile("ldmatrix.sync.aligned.m8n8.x4.shared.b16 {%0,%1,%2,%3}, [%4];"
                 : "=r"(r[0]), "=r"(r[1]), "=r"(r[2]), "=r"(r[3]) : "r"(addr));
}
__device__ __forceinline__ void mma16816(float* c, const uint32_t* a, uint32_t b0, uint32_t b1) {
    asm volatile("mma.sync.aligned.m16n8k16.row.col.f32.f16.f16.f32 "
                 "{%0,%1,%2,%3},{%4,%5,%6,%7},{%8,%9},{%0,%1,%2,%3};"
                 : "+f"(c[0]), "+f"(c[1]), "+f"(c[2]), "+f"(c[3])
                 : "r"(a[0]), "r"(a[1]), "r"(a[2]), "r"(a[3]), "r"(b0), "r"(b1));
}
__device__ __forceinline__ void cp16(uint32_t dst, const void* src) {
    asm volatile("cp.async.cg.shared.global [%0], [%1], 16;" :: "r"(dst), "l"(src));
}
__device__ __forceinline__ void cp_commit() { asm volatile("cp.async.commit_group;"); }
__device__ __forceinline__ void cp_wait0() { asm volatile("cp.async.wait_group 0;" ::: "memory"); }

// SMEM layout (bytes); all strides 72 halves = 144 B (16B-aligned, conflict-free ldmatrix)
#define A_STRIDE 72
#define OFF_A 0
#define OFF_W1 9216
#define OFF_W2 (9216 + 18432)              // 4 chunks x [64][72]
#define OFF_GPART (OFF_W2 + 36864)         // float [64][4]
#define OFF_GATE (OFF_GPART + 1024)        // float [64]
#define OFF_ATTN (OFF_GATE + 256)          // float [64]
#define SMEM_TOTAL (OFF_ATTN + 256 + 64)

__global__ __launch_bounds__(THREADS, 2)
void fusion_main(const float* __restrict__ vert, const float* __restrict__ horiz,
                 const unsigned char* __restrict__ mask,
                 const float* __restrict__ gb1, const float* __restrict__ gw2,
                 const float* __restrict__ gb2,
                 const float* __restrict__ ab1, const float* __restrict__ aw2,
                 const float* __restrict__ ab2,
                 float* __restrict__ out_fused, float* __restrict__ out_pm,
                 float* __restrict__ out_attn) {
    extern __shared__ char smem[];
    __half* As = (__half*)(smem + OFF_A);
    __half* W1s = (__half*)(smem + OFF_W1);
    float* gpart = (float*)(smem + OFF_GPART);
    float* gate_s = (float*)(smem + OFF_GATE);
    float* attn_s = (float*)(smem + OFF_ATTN);

    const int tid = threadIdx.x;
    const int wid = tid >> 5;
    const int lane = tid & 31;
    const int cta = blockIdx.x;          // 2 lb pairs: lb = cta*2 + lbi
    const uint32_t sbase = smem_u32(smem);

    // warp grid 2m x 4n; warp tiles: GEMM1 m32xn32, GEMM2(fused) m32xn16
    const int mg = wid >> 2;
    const int ng = wid & 3;

    const int lgrp = lane >> 3;
    const int lrow = (lane & 7) + (lgrp & 1) * 8;
    const int lcol = (lgrp >> 1) * 8;
    const int bn_off = ((lane >> 4) & 1) * 8 + (lane & 7);
    const int bk_off = ((lane >> 3) & 1) * 8;

    // ---- stage W2 persistent (4 k-chunks of [64][72]) via cp.async ----
#pragma unroll
    for (int t = 0; t < 8; t++) {
        int j = tid + t * THREADS;       // 0..2047 = 4 kc x 64 n x 8 q
        int kc = j >> 9;
        int n = (j >> 3) & 63;
        int q = j & 7;
        cp16(sbase + OFF_W2 + kc * 9216 + n * 144 + q * 16,
             g_w2h + n * Dq + kc * 64 + q * 8);
    }
    cp_commit();

    // ========== GEMM1 + fused GEMM2 (Yv/Yh) over 8 k64 chunks ==========
    float acc1[2][4][4];
    float accv[2][2][4], acch[2][2][4];
#pragma unroll
    for (int a = 0; a < 2; a++) {
#pragma unroll
        for (int b = 0; b < 4; b++)
#pragma unroll
            for (int c = 0; c < 4; c++) acc1[a][b][c] = 0.f;
#pragma unroll
        for (int b = 0; b < 2; b++)
#pragma unroll
            for (int c = 0; c < 4; c++) { accv[a][b][c] = 0.f; acch[a][b][c] = 0.f; }
    }

#pragma unroll 1
    for (int chunk = 0; chunk < 8; chunk++) {
        const float* feat = (chunk < 4) ? vert : horiz;
        const int kb = (chunk & 3) * 64;
        __syncthreads();
        // W1 chunk via cp.async (issue first, overlap with A conversion)
#pragma unroll
        for (int t = 0; t < 4; t++) {
            int j = tid + t * THREADS;   // 0..1023 = 128 n x 8 q
            int n = j >> 3;
            int q = j & 7;
            cp16(sbase + OFF_W1 + n * 144 + q * 16,
                 g_w1h + n * KC + chunk * 64 + q * 8);
        }
        cp_commit();
        // stage A chunk: 64 m x 64 k fp32 -> fp16
        const float4* src = (const float4*)(feat + (size_t)cta * 64 * Dq);
#pragma unroll
        for (int t = 0; t < 4; t++) {
            int j = tid + t * THREADS;   // 0..1023
            int m = j >> 4;
            int kq = (j & 15) * 4;
            float4 v = src[m * (Dq / 4) + (kb + kq) / 4];
            __half2 h01 = __floats2half2_rn(v.x, v.y);
            __half2 h23 = __floats2half2_rn(v.z, v.w);
            *(uint2*)&As[m * A_STRIDE + kq] =
                make_uint2(*(uint32_t*)&h01, *(uint32_t*)&h23);
        }
        cp_wait0();
        __syncthreads();

#pragma unroll
        for (int ks = 0; ks < 4; ks++) {
            const int kk = ks * 16;
            uint32_t a[2][4];
#pragma unroll
            for (int mt = 0; mt < 2; mt++) {
                int row = mg * 32 + mt * 16 + lrow;
                ldmatrix_x4(a[mt], smem_u32(&As[row * A_STRIDE + kk + lcol]));
            }
            // GEMM1: B1 from W1 chunk
#pragma unroll
            for (int nh = 0; nh < 2; nh++) {
                uint32_t b[4];
                ldmatrix_x4(b, smem_u32(&W1s[(ng * 32 + nh * 16 + bn_off) * A_STRIDE + kk + bk_off]));
#pragma unroll
                for (int nf2 = 0; nf2 < 2; nf2++) {
                    int nf = nh * 2 + nf2;
#pragma unroll
                    for (int mt = 0; mt < 2; mt++)
                        mma16816(acc1[mt][nf], a[mt], b[nf2 * 2], b[nf2 * 2 + 1]);
                }
            }
            // fused GEMM2: B2 from persistent W2 (k-slice = chunk&3), A frags reused
            {
                uint32_t b2[4];
                uint32_t addr = sbase + OFF_W2 + (chunk & 3) * 9216 +
                                (ng * 16 + bn_off) * 144 + (kk + bk_off) * 2;
                ldmatrix_x4(b2, addr);
                if (chunk < 4) {
#pragma unroll
                    for (int nf = 0; nf < 2; nf++)
#pragma unroll
                        for (int mt = 0; mt < 2; mt++)
                            mma16816(accv[mt][nf], a[mt], b2[nf * 2], b2[nf * 2 + 1]);
                } else {
#pragma unroll
                    for (int nf = 0; nf < 2; nf++)
#pragma unroll
                        for (int mt = 0; mt < 2; mt++)
                            mma16816(acch[mt][nf], a[mt], b2[nf * 2], b2[nf * 2 + 1]);
                }
            }
        }
    }

    // ---- gate epilogue: relu(C1+gb1) . gw2 -> sigmoid ----
    {
        float p0[2] = {0.f, 0.f}, p1[2] = {0.f, 0.f};
#pragma unroll
        for (int nf = 0; nf < 4; nf++) {
#pragma unroll
            for (int j = 0; j < 2; j++) {
                int n = ng * 32 + nf * 8 + 2 * (lane & 3) + j;
                float b1v = __ldg(&gb1[n]);
                float w2v = __ldg(&gw2[n]);
#pragma unroll
                for (int mt = 0; mt < 2; mt++) {
                    p0[mt] += fmaxf(acc1[mt][nf][j] + b1v, 0.f) * w2v;
                    p1[mt] += fmaxf(acc1[mt][nf][j + 2] + b1v, 0.f) * w2v;
                }
            }
        }
#pragma unroll
        for (int o = 1; o <= 2; o <<= 1) {
#pragma unroll
            for (int mt = 0; mt < 2; mt++) {
                p0[mt] += __shfl_xor_sync(0xffffffffu, p0[mt], o);
                p1[mt] += __shfl_xor_sync(0xffffffffu, p1[mt], o);
            }
        }
        if ((lane & 3) == 0) {
            int r = lane >> 2;
#pragma unroll
            for (int mt = 0; mt < 2; mt++) {
                gpart[(mg * 32 + mt * 16 + r) * 4 + ng] = p0[mt];
                gpart[(mg * 32 + mt * 16 + 8 + r) * 4 + ng] = p1[mt];
            }
        }
        __syncthreads();
        if (tid < 64) {
            float s = gpart[tid * 4] + gpart[tid * 4 + 1] + gpart[tid * 4 + 2] + gpart[tid * 4 + 3];
            s += __ldg(gb2);
            gate_s[tid] = 1.f / (1.f + __expf(-s));
        }
        __syncthreads();
    }

    // ---- logits epilogue: tanh(g*Yv + (1-g)*Yh + ab1) . aw2 ----
    {
        float p0[2] = {0.f, 0.f}, p1[2] = {0.f, 0.f};
        int r = lane >> 2;
        float gA[2], gB[2];  // gates for rows r and r+8 of each mt
#pragma unroll
        for (int mt = 0; mt < 2; mt++) {
            gA[mt] = gate_s[mg * 32 + mt * 16 + r];
            gB[mt] = gate_s[mg * 32 + mt * 16 + 8 + r];
        }
#pragma unroll
        for (int nf = 0; nf < 2; nf++) {
#pragma unroll
            for (int j = 0; j < 2; j++) {
                int n = ng * 16 + nf * 8 + 2 * (lane & 3) + j;
                float b1v = __ldg(&ab1[n]);
                float w2v = __ldg(&aw2[n]);
#pragma unroll
                for (int mt = 0; mt < 2; mt++) {
                    float yv0 = accv[mt][nf][j], yh0 = acch[mt][nf][j];
                    float pre0 = fmaf(gA[mt], yv0 - yh0, yh0) + b1v;
                    p0[mt] += tanhf(pre0) * w2v;
                    float yv1 = accv[mt][nf][j + 2], yh1 = acch[mt][nf][j + 2];
                    float pre1 = fmaf(gB[mt], yv1 - yh1, yh1) + b1v;
                    p1[mt] += tanhf(pre1) * w2v;
                }
            }
        }
#pragma unroll
        for (int o = 1; o <= 2; o <<= 1) {
#pragma unroll
            for (int mt = 0; mt < 2; mt++) {
                p0[mt] += __shfl_xor_sync(0xffffffffu, p0[mt], o);
                p1[mt] += __shfl_xor_sync(0xffffffffu, p1[mt], o);
            }
        }
        if ((lane & 3) == 0) {
#pragma unroll
            for (int mt = 0; mt < 2; mt++) {
                gpart[(mg * 32 + mt * 16 + r) * 4 + ng] = p0[mt];
                gpart[(mg * 32 + mt * 16 + 8 + r) * 4 + ng] = p1[mt];
            }
        }
        __syncthreads();
    }

    // ---- masked softmax per lb (2 warps; lane = msg) ----
    if (tid < 64) {
        int lbi = tid >> 5;
        int msg = tid & 31;
        int lb = cta * 2 + lbi;
        int l = lb >> 3, b = lb & 7;
        float lg = gpart[tid * 4] + gpart[tid * 4 + 1] + gpart[tid * 4 + 2] + gpart[tid * 4 + 3];
        lg += __ldg(ab2);
        size_t midx = ((size_t)b * Nq + msg) * Lq + l;
        int mode = g_mask_mode;
        bool valid;
        if (mode == 2)      valid = ((const float*)mask)[midx] != 0.0f;
        else if (mode == 1) valid = ((const int*)mask)[midx] != 0;
        else                valid = mask[midx] != 0;
        float mv = valid ? lg : -FLT_MAX;
#pragma unroll
        for (int o = 16; o >= 1; o >>= 1)
            mv = fmaxf(mv, __shfl_xor_sync(0xffffffffu, mv, o));
        float e = valid ? __expf(lg - mv) : 0.f;
        float s = e;
#pragma unroll
        for (int o = 16; o >= 1; o >>= 1)
            s += __shfl_xor_sync(0xffffffffu, s, o);
        float a = (s > 0.f) ? e / s : 0.f;
        attn_s[tid] = a;
        out_attn[((size_t)b * Lq + l) * Nq + msg] = a;
    }
    __syncthreads();

    // ---- blend + fused in one pass: p = g*v+(1-g)*h -> pm; fused += attn*p ----
#pragma unroll 1
    for (int it = 0; it < 2; it++) {
        int idx = tid + it * THREADS;    // 0..511 = 2 lb x 256 d
        int lbi = idx >> 8;
        int d = idx & 255;
        size_t base = (size_t)(cta * 64 + lbi * 32) * Dq + d;
        const float* vb = vert + base;
        const float* hb = horiz + base;
        float* pmb = out_pm + base;
        float f = 0.f;
#pragma unroll
        for (int m = 0; m < Nq; m++) {
            float g = gate_s[lbi * 32 + m];
            float v = vb[m * Dq];
            float h = hb[m * Dq];
            float p = fmaf(g, v - h, h);
            pmb[m * Dq] = p;
            f = fmaf(attn_s[lbi * 32 + m], p, f);
        }
        out_fused[(size_t)cta * 512 + idx] = f;
    }
}

extern "C" void kernel_launch(void* const* d_in, const int* in_sizes, int n_in,
                              void* d_out, int out_size) {
    const float* vert = (const float*)d_in[0];
    const float* horiz = (const float*)d_in[1];
    const unsigned char* mask = (const unsigned char*)d_in[2];
    const float* gw1 = (const float*)d_in[3];
    const float* gb1 = (const float*)d_in[4];
    const float* gw2 = (const float*)d_in[5];
    const float* gb2 = (const float*)d_in[6];
    const float* aw1 = (const float*)d_in[7];
    const float* ab1 = (const float*)d_in[8];
    const float* aw2 = (const float*)d_in[9];
    const float* ab2 = (const float*)d_in[10];

    float* out = (float*)d_out;
    float* out_fused = out;                                   // L*B*D
    float* out_pm = out + (size_t)Lq * Bq * Dq;               // L*B*N*D
    float* out_attn = out_pm + (size_t)Lq * Bq * Nq * Dq;     // B*L*N

    prep_kernel<<<(GHq * KC + 255) / 256, 256>>>(gw1, aw1, mask);

    cudaFuncSetAttribute(fusion_main, cudaFuncAttributeMaxDynamicSharedMemorySize, SMEM_TOTAL);
    fusion_main<<<Lq * Bq / 2, THREADS, SMEM_TOTAL>>>(vert, horiz, mask,
                                                      gb1, gw2, gb2, ab1, aw2, ab2,
                                                      out_fused, out_pm, out_attn);
}